// round 7
// baseline (speedup 1.0000x reference)
#include <cuda_runtime.h>
#include <math.h>

#define Nn     16384
#define D_INc  256
#define HIDD   256
#define D_OUTc 256
#define Ff     8
#define Ll     4
#define IN_CH  272          // 2*8 + 256
#define GAMMAf 0.5f

// ---------------- device scratch (no allocations allowed) ----------------
__device__ __align__(16) float g_cs[2][Ll][Ff];
__device__ __align__(16) float g_Hm[Nn][16];      // cols 0-7: tri, 8-15: cl4

__device__ __forceinline__ float softplusf(float x) {
    return (x > 20.f) ? x : log1pf(expf(x));
}

__device__ __forceinline__ void red4(float* p, float a, float b, float c, float d) {
    asm volatile("red.global.add.v4.f32 [%0], {%1, %2, %3, %4};"
                 :: "l"(p), "f"(a), "f"(b), "f"(c), "f"(d) : "memory");
}

// packed dual-fp32 FMA (Blackwell f32x2) -------------------------------
#define FFMA2(acc, a, b) \
    asm("fma.rn.f32x2 %0, %1, %2, %0;" : "+l"(acc) : "l"(a), "l"(b))
#define DUP2(p, x) \
    asm("mov.b64 %0, {%1, %1};" : "=l"(p) : "r"(x))
#define UNPK2(lo, hi, p) \
    asm("mov.b64 {%0, %1}, %2;" : "=r"(lo), "=r"(hi) : "l"(p))

// ---------------- kernel 1: filter traces + coefficients ----------------
__global__ void setup_kernel(const float* __restrict__ Wt,
                             const float* __restrict__ Wc,
                             const float* __restrict__ lg) {
    int t = threadIdx.x;
    if (t >= 16) return;
    int which = t >> 3;
    int f = t & 7;
    int S = which ? 4 : 3;
    const float* W = which ? (Wc + f * 16) : (Wt + f * 9);

    float Wm[4][4], Sf[4][4];
    for (int i = 0; i < S; i++)
        for (int j = 0; j < S; j++)
            Wm[i][j] = softplusf(W[i * S + j]);
    for (int i = 0; i < S; i++)
        for (int j = 0; j < S; j++)
            Sf[i][j] = 0.5f * (Wm[i][j] + Wm[j][i]);
    for (int i = 0; i < S; i++) Sf[i][i] = 0.f;
    for (int i = 0; i < S; i++) {
        float rs = 0.f;
        for (int j = 0; j < S; j++) rs += Sf[i][j];
        float inv = 1.f / fmaxf(rs, 1e-12f);
        for (int j = 0; j < S; j++) Sf[i][j] *= inv;
    }
    float P[4][4], Q[4][4], tr[Ll];
    for (int i = 0; i < S; i++)
        for (int j = 0; j < S; j++) P[i][j] = Sf[i][j];
    for (int l = 0; l < Ll; l++) {
        if (l) {
            for (int i = 0; i < S; i++)
                for (int j = 0; j < S; j++) {
                    float a = 0.f;
                    for (int k = 0; k < S; k++) a += P[i][k] * Sf[k][j];
                    Q[i][j] = a;
                }
            for (int i = 0; i < S; i++)
                for (int j = 0; j < S; j++) P[i][j] = Q[i][j];
        }
        float s = 0.f;
        for (int i = 0; i < S; i++) s += P[i][i];
        tr[l] = s;
    }
    for (int l = 0; l < Ll; l++) {
        float coeff = powf(GAMMAf, (float)(l + 1)) * softplusf(lg[l]);
        g_cs[which][l][f] = tr[l] * coeff;
    }
}

// ---------------- kernel 2: zero the motif accumulator ----------------
__global__ void zero_kernel() {
    int i = blockIdx.x * blockDim.x + threadIdx.x;
    if (i < Nn * 16) ((float*)g_Hm)[i] = 0.f;
}

// ---------------- motif response ----------------
template <int S>
__device__ __forceinline__ void motif_body(const float* __restrict__ A,
                                           const int* __restrict__ nodes,
                                           int M, int which, int bid) {
    int m = bid * 256 + threadIdx.x;
    if (m >= M) return;

    int nd[S];
#pragma unroll
    for (int i = 0; i < S; i++) nd[i] = nodes[m * S + i];

    float T[S][S];
#pragma unroll
    for (int i = 0; i < S; i++) {
        const float* rowp = A + (size_t)nd[i] * Nn;
#pragma unroll
        for (int j = 0; j < S; j++) T[i][j] = __ldg(rowp + nd[j]);
    }
#pragma unroll
    for (int i = 0; i < S; i++) {
        float rs = 0.f;
#pragma unroll
        for (int j = 0; j < S; j++) rs += T[i][j];
        float inv = 1.f / fmaxf(rs, 1e-12f);
#pragma unroll
        for (int j = 0; j < S; j++) T[i][j] *= inv;
    }

    float P[S][S], Q[S][S], tr[Ll];
#pragma unroll
    for (int i = 0; i < S; i++)
#pragma unroll
        for (int j = 0; j < S; j++) P[i][j] = T[i][j];
    {
        float s = 0.f;
#pragma unroll
        for (int i = 0; i < S; i++) s += P[i][i];
        tr[0] = s;
    }
#pragma unroll
    for (int l = 1; l < Ll; l++) {
#pragma unroll
        for (int i = 0; i < S; i++)
#pragma unroll
            for (int j = 0; j < S; j++) {
                float a = 0.f;
#pragma unroll
                for (int k = 0; k < S; k++) a += P[i][k] * T[k][j];
                Q[i][j] = a;
            }
        float s = 0.f;
#pragma unroll
        for (int i = 0; i < S; i++) {
#pragma unroll
            for (int j = 0; j < S; j++) P[i][j] = Q[i][j];
            s += P[i][i];
        }
        tr[l] = s;
    }

    float sims[Ff];
#pragma unroll
    for (int f = 0; f < Ff; f++) {
        float s = 0.f;
#pragma unroll
        for (int l = 0; l < Ll; l++) s += tr[l] * g_cs[which][l][f];
        sims[f] = s;
    }
    float mx = sims[0];
#pragma unroll
    for (int f = 1; f < Ff; f++) mx = fmaxf(mx, sims[f]);
    float e[Ff], es = 0.f;
#pragma unroll
    for (int f = 0; f < Ff; f++) { e[f] = expf(sims[f] - mx); es += e[f]; }
    float invs = 1.f / es;
    const float invS = 1.f / (float)S;
    float cb[Ff];
#pragma unroll
    for (int f = 0; f < Ff; f++) cb[f] = e[f] * invs * sims[f] * invS;

    int off = which * 8;
#pragma unroll
    for (int i = 0; i < S; i++) {
        float* p = &g_Hm[nd[i]][off];
        red4(p,     cb[0], cb[1], cb[2], cb[3]);
        red4(p + 4, cb[4], cb[5], cb[6], cb[7]);
    }
}

__global__ void motif_all_kernel(const float* __restrict__ A,
                                 const int* __restrict__ nt, int Mt, int nb3,
                                 const int* __restrict__ nc, int Mc) {
    if ((int)blockIdx.x < nb3)
        motif_body<3>(A, nt, Mt, 0, blockIdx.x);
    else
        motif_body<4>(A, nc, Mc, 1, blockIdx.x - nb3);
}

// ---------------- fused concat + LN + MLP ----------------
// 32 rows/block, 128 threads, 8x8 tile, transposed x, double-buffered W.
#define ROWS  32
#define TPB   128
#define BK    8
#define XS    36                  // padded row stride in sXT (mult of 4)

__global__ __launch_bounds__(TPB, 4) void mlp_kernel(
    const float* __restrict__ H_in, const float* __restrict__ ln_g,
    const float* __restrict__ ln_b,
    const float* __restrict__ W1, const float* __restrict__ b1,
    const float* __restrict__ W2, const float* __restrict__ b2,
    float* __restrict__ out) {
    __shared__ float sXT[IN_CH * XS];      // [k][row]
    __shared__ float sW[2][BK * HIDD];     // double-buffered W tile

    const int tid  = threadIdx.x;
    const int warp = tid >> 5;
    const int lane = tid & 31;
    const int rbase = blockIdx.x * ROWS;

    const int r0  = warp * 8;
    const int c0a = lane * 4;
    const int c0b = 128 + lane * 4;

    float4 pf[4];
#define LDG_TILE(Wp, kbase)                                                  \
    {                                                                        \
        _Pragma("unroll")                                                    \
        for (int q = 0; q < 4; q++) {                                        \
            int p = q * TPB + tid;                                           \
            int kk = p >> 6, cc = (p & 63) << 2;                             \
            pf[q] = *(const float4*)&Wp[(size_t)((kbase) + kk) * HIDD + cc]; \
        }                                                                    \
    }
#define STS_TILE(BUF)                                                        \
    {                                                                        \
        _Pragma("unroll")                                                    \
        for (int q = 0; q < 4; q++) {                                        \
            int p = q * TPB + tid;                                           \
            int kk = p >> 6, cc = (p & 63) << 2;                             \
            *(float4*)&sW[BUF][kk * HIDD + cc] = pf[q];                      \
        }                                                                    \
    }
#define COMPUTE_TILE(K0, BUF)                                                \
    {                                                                        \
        _Pragma("unroll")                                                    \
        for (int kk = 0; kk < BK; kk++) {                                    \
            const float* xb = &sXT[(K0 + kk) * XS + r0];                     \
            float4 xa = *(const float4*)xb;                                  \
            float4 xc = *(const float4*)(xb + 4);                            \
            unsigned long long xp[8];                                        \
            DUP2(xp[0], __float_as_uint(xa.x));                              \
            DUP2(xp[1], __float_as_uint(xa.y));                              \
            DUP2(xp[2], __float_as_uint(xa.z));                              \
            DUP2(xp[3], __float_as_uint(xa.w));                              \
            DUP2(xp[4], __float_as_uint(xc.x));                              \
            DUP2(xp[5], __float_as_uint(xc.y));                              \
            DUP2(xp[6], __float_as_uint(xc.z));                              \
            DUP2(xp[7], __float_as_uint(xc.w));                              \
            ulonglong2 wA = *(ulonglong2*)&sW[BUF][kk * HIDD + c0a];         \
            ulonglong2 wB = *(ulonglong2*)&sW[BUF][kk * HIDD + c0b];         \
            _Pragma("unroll")                                                \
            for (int i = 0; i < 8; i++) {                                    \
                FFMA2(acc[i][0], xp[i], wA.x);                               \
                FFMA2(acc[i][1], xp[i], wA.y);                               \
                FFMA2(acc[i][2], xp[i], wB.x);                               \
                FFMA2(acc[i][3], xp[i], wB.y);                               \
            }                                                                \
        }                                                                    \
    }

    // prefetch W1 tile 0 — latency hides under LN
    LDG_TILE(W1, 0);

    // ---- LN: single gmem read, values kept in registers ----
    {
#pragma unroll
        for (int i = 0; i < 8; i++) {
            int r = r0 + i;
            int grow = rbase + r;
            const float* hrow = H_in + (size_t)grow * D_INc;
            float vloc[9];
            float s = 0.f, s2 = 0.f;
#pragma unroll
            for (int q = 0; q < 9; q++) {
                int c = lane + q * 32;
                if (c < IN_CH) {
                    float v = (c < 16) ? g_Hm[grow][c] : __ldg(hrow + (c - 16));
                    vloc[q] = v;
                    s += v; s2 += v * v;
                }
            }
#pragma unroll
            for (int o = 16; o; o >>= 1) {
                s  += __shfl_xor_sync(0xffffffffu, s, o);
                s2 += __shfl_xor_sync(0xffffffffu, s2, o);
            }
            float mu = s * (1.f / IN_CH);
            float var = s2 * (1.f / IN_CH) - mu * mu;
            float rstd = rsqrtf(var + 1e-5f);
#pragma unroll
            for (int q = 0; q < 9; q++) {
                int c = lane + q * 32;
                if (c < IN_CH)
                    sXT[c * XS + r] = (vloc[q] - mu) * rstd * ln_g[c] + ln_b[c];
            }
        }
    }
    STS_TILE(0);
    __syncthreads();

    unsigned long long acc[8][4];
#pragma unroll
    for (int i = 0; i < 8; i++)
#pragma unroll
        for (int j = 0; j < 4; j++) acc[i][j] = 0ULL;

    // ---- GEMM1: x(32x272) @ W1(272x256), double-buffered, 1 sync/tile ----
    {
        const int NT = IN_CH / BK;       // 34
        for (int t = 0; t < NT; t++) {
            if (t + 1 < NT) LDG_TILE(W1, (t + 1) * BK);
            COMPUTE_TILE(t * BK, t & 1);
            if (t + 1 < NT) STS_TILE((t + 1) & 1);
            __syncthreads();
        }
    }

    // prefetch W2 tile 0 — latency hides under GELU math
    LDG_TILE(W2, 0);

    // ---- bias + exact GELU -> transposed hidden into sXT ----
    {
        const float4 bA = *(const float4*)&b1[c0a];
        const float4 bB = *(const float4*)&b1[c0b];
        const float bb[8] = {bA.x, bA.y, bA.z, bA.w, bB.x, bB.y, bB.z, bB.w};
        float v[8][8];
#pragma unroll
        for (int i = 0; i < 8; i++)
#pragma unroll
            for (int j = 0; j < 4; j++) {
                unsigned lo, hi;
                UNPK2(lo, hi, acc[i][j]);
                float x0 = __uint_as_float(lo) + bb[j * 2];
                float x1 = __uint_as_float(hi) + bb[j * 2 + 1];
                v[i][j * 2]     = 0.5f * x0 * (1.f + erff(x0 * 0.7071067811865475f));
                v[i][j * 2 + 1] = 0.5f * x1 * (1.f + erff(x1 * 0.7071067811865475f));
                acc[i][j] = 0ULL;
            }
#pragma unroll
        for (int j = 0; j < 8; j++) {
            int c = (j < 4) ? (c0a + j) : (c0b + j - 4);
            *(float4*)&sXT[c * XS + r0] =
                make_float4(v[0][j], v[1][j], v[2][j], v[3][j]);
            *(float4*)&sXT[c * XS + r0 + 4] =
                make_float4(v[4][j], v[5][j], v[6][j], v[7][j]);
        }
    }
    STS_TILE(0);
    __syncthreads();

    // ---- GEMM2: h(32x256) @ W2(256x256) ----
    {
        const int NT = HIDD / BK;        // 32
        for (int t = 0; t < NT; t++) {
            if (t + 1 < NT) LDG_TILE(W2, (t + 1) * BK);
            COMPUTE_TILE(t * BK, t & 1);
            if (t + 1 < NT) STS_TILE((t + 1) & 1);
            __syncthreads();
        }
    }

    // ---- bias + store ----
    {
        const float4 bA = *(const float4*)&b2[c0a];
        const float4 bB = *(const float4*)&b2[c0b];
#pragma unroll
        for (int i = 0; i < 8; i++) {
            unsigned lo, hi;
            float v[8];
#pragma unroll
            for (int j = 0; j < 4; j++) {
                UNPK2(lo, hi, acc[i][j]);
                v[j * 2]     = __uint_as_float(lo);
                v[j * 2 + 1] = __uint_as_float(hi);
            }
            size_t base = (size_t)(rbase + r0 + i) * D_OUTc;
            *(float4*)&out[base + c0a] =
                make_float4(v[0] + bA.x, v[1] + bA.y, v[2] + bA.z, v[3] + bA.w);
            *(float4*)&out[base + c0b] =
                make_float4(v[4] + bB.x, v[5] + bB.y, v[6] + bB.z, v[7] + bB.w);
        }
    }
}

// ---------------- launch ----------------
extern "C" void kernel_launch(void* const* d_in, const int* in_sizes, int n_in,
                              void* d_out, int out_size) {
    const float* A       = (const float*)d_in[0];
    const float* H_in    = (const float*)d_in[1];
    const float* Wt      = (const float*)d_in[2];
    const float* Wc      = (const float*)d_in[3];
    const float* lg      = (const float*)d_in[4];
    const float* ln_g    = (const float*)d_in[5];
    const float* ln_b    = (const float*)d_in[6];
    const float* W1      = (const float*)d_in[7];
    const float* b1      = (const float*)d_in[8];
    const float* W2      = (const float*)d_in[9];
    const float* b2      = (const float*)d_in[10];
    const int* nodes_tri = (const int*)d_in[11];
    const int* nodes_cl4 = (const int*)d_in[12];
    float* out = (float*)d_out;

    int M_tri = in_sizes[11] / 3;
    int M_cl4 = in_sizes[12] / 4;
    int nb3 = (M_tri + 255) / 256;
    int nb4 = (M_cl4 + 255) / 256;

    setup_kernel<<<1, 32>>>(Wt, Wc, lg);
    zero_kernel<<<(Nn * 16 + 255) / 256, 256>>>();
    motif_all_kernel<<<nb3 + nb4, 256>>>(A, nodes_tri, M_tri, nb3, nodes_cl4, M_cl4);
    mlp_kernel<<<Nn / ROWS, TPB>>>(H_in, ln_g, ln_b, W1, b1, W2, b2, out);
}

// round 9
// speedup vs baseline: 1.6803x; 1.6803x over previous
#include <cuda_runtime.h>
#include <math.h>

#define Nn     16384
#define D_INc  256
#define HIDD   256
#define D_OUTc 256
#define Ff     8
#define Ll     4
#define IN_CH  272          // 2*8 + 256
#define GAMMAf 0.5f

// ---------------- device scratch (no allocations allowed) ----------------
__device__ __align__(16) float g_cs[2][Ll][Ff];
__device__ __align__(16) float g_Hm[Nn][16];      // cols 0-7: tri, 8-15: cl4

__device__ __forceinline__ float softplusf(float x) {
    return (x > 20.f) ? x : log1pf(expf(x));
}

__device__ __forceinline__ void red4(float* p, float a, float b, float c, float d) {
    asm volatile("red.global.add.v4.f32 [%0], {%1, %2, %3, %4};"
                 :: "l"(p), "f"(a), "f"(b), "f"(c), "f"(d) : "memory");
}

// packed dual-fp32 FMA (Blackwell f32x2) -------------------------------
#define FFMA2(acc, a, b) \
    asm("fma.rn.f32x2 %0, %1, %2, %0;" : "+l"(acc) : "l"(a), "l"(b))
#define DUP2(p, x) \
    asm("mov.b64 %0, {%1, %1};" : "=l"(p) : "r"(x))
#define UNPK2(lo, hi, p) \
    asm("mov.b64 {%0, %1}, %2;" : "=r"(lo), "=r"(hi) : "l"(p))

// register-free async gmem->smem 16B copy (LDGSTS)
#define CPA16(dst, src) do {                                              \
    unsigned _s = (unsigned)__cvta_generic_to_shared(dst);                \
    asm volatile("cp.async.cg.shared.global [%0], [%1], 16;"              \
                 :: "r"(_s), "l"(src));                                   \
} while (0)
#define CP_COMMIT() asm volatile("cp.async.commit_group;" ::: "memory")
#define CP_WAIT0()  asm volatile("cp.async.wait_group 0;" ::: "memory")

// ---------------- kernel 1: filter traces + coefficients ----------------
__global__ void setup_kernel(const float* __restrict__ Wt,
                             const float* __restrict__ Wc,
                             const float* __restrict__ lg) {
    int t = threadIdx.x;
    if (t >= 16) return;
    int which = t >> 3;
    int f = t & 7;
    int S = which ? 4 : 3;
    const float* W = which ? (Wc + f * 16) : (Wt + f * 9);

    float Wm[4][4], Sf[4][4];
    for (int i = 0; i < S; i++)
        for (int j = 0; j < S; j++)
            Wm[i][j] = softplusf(W[i * S + j]);
    for (int i = 0; i < S; i++)
        for (int j = 0; j < S; j++)
            Sf[i][j] = 0.5f * (Wm[i][j] + Wm[j][i]);
    for (int i = 0; i < S; i++) Sf[i][i] = 0.f;
    for (int i = 0; i < S; i++) {
        float rs = 0.f;
        for (int j = 0; j < S; j++) rs += Sf[i][j];
        float inv = 1.f / fmaxf(rs, 1e-12f);
        for (int j = 0; j < S; j++) Sf[i][j] *= inv;
    }
    float P[4][4], Q[4][4], tr[Ll];
    for (int i = 0; i < S; i++)
        for (int j = 0; j < S; j++) P[i][j] = Sf[i][j];
    for (int l = 0; l < Ll; l++) {
        if (l) {
            for (int i = 0; i < S; i++)
                for (int j = 0; j < S; j++) {
                    float a = 0.f;
                    for (int k = 0; k < S; k++) a += P[i][k] * Sf[k][j];
                    Q[i][j] = a;
                }
            for (int i = 0; i < S; i++)
                for (int j = 0; j < S; j++) P[i][j] = Q[i][j];
        }
        float s = 0.f;
        for (int i = 0; i < S; i++) s += P[i][i];
        tr[l] = s;
    }
    for (int l = 0; l < Ll; l++) {
        float coeff = powf(GAMMAf, (float)(l + 1)) * softplusf(lg[l]);
        g_cs[which][l][f] = tr[l] * coeff;
    }
}

// ---------------- kernel 2: zero the motif accumulator ----------------
__global__ void zero_kernel() {
    int i = blockIdx.x * blockDim.x + threadIdx.x;
    if (i < Nn * 16) ((float*)g_Hm)[i] = 0.f;
}

// ---------------- motif response ----------------
template <int S>
__device__ __forceinline__ void motif_body(const float* __restrict__ A,
                                           const int* __restrict__ nodes,
                                           int M, int which, int bid) {
    int m = bid * 256 + threadIdx.x;
    if (m >= M) return;

    int nd[S];
#pragma unroll
    for (int i = 0; i < S; i++) nd[i] = nodes[m * S + i];

    float T[S][S];
#pragma unroll
    for (int i = 0; i < S; i++) {
        const float* rowp = A + (size_t)nd[i] * Nn;
#pragma unroll
        for (int j = 0; j < S; j++) T[i][j] = __ldg(rowp + nd[j]);
    }
#pragma unroll
    for (int i = 0; i < S; i++) {
        float rs = 0.f;
#pragma unroll
        for (int j = 0; j < S; j++) rs += T[i][j];
        float inv = 1.f / fmaxf(rs, 1e-12f);
#pragma unroll
        for (int j = 0; j < S; j++) T[i][j] *= inv;
    }

    float P[S][S], Q[S][S], tr[Ll];
#pragma unroll
    for (int i = 0; i < S; i++)
#pragma unroll
        for (int j = 0; j < S; j++) P[i][j] = T[i][j];
    {
        float s = 0.f;
#pragma unroll
        for (int i = 0; i < S; i++) s += P[i][i];
        tr[0] = s;
    }
#pragma unroll
    for (int l = 1; l < Ll; l++) {
#pragma unroll
        for (int i = 0; i < S; i++)
#pragma unroll
            for (int j = 0; j < S; j++) {
                float a = 0.f;
#pragma unroll
                for (int k = 0; k < S; k++) a += P[i][k] * T[k][j];
                Q[i][j] = a;
            }
        float s = 0.f;
#pragma unroll
        for (int i = 0; i < S; i++) {
#pragma unroll
            for (int j = 0; j < S; j++) P[i][j] = Q[i][j];
            s += P[i][i];
        }
        tr[l] = s;
    }

    float sims[Ff];
#pragma unroll
    for (int f = 0; f < Ff; f++) {
        float s = 0.f;
#pragma unroll
        for (int l = 0; l < Ll; l++) s += tr[l] * g_cs[which][l][f];
        sims[f] = s;
    }
    float mx = sims[0];
#pragma unroll
    for (int f = 1; f < Ff; f++) mx = fmaxf(mx, sims[f]);
    float e[Ff], es = 0.f;
#pragma unroll
    for (int f = 0; f < Ff; f++) { e[f] = expf(sims[f] - mx); es += e[f]; }
    float invs = 1.f / es;
    const float invS = 1.f / (float)S;
    float cb[Ff];
#pragma unroll
    for (int f = 0; f < Ff; f++) cb[f] = e[f] * invs * sims[f] * invS;

    int off = which * 8;
#pragma unroll
    for (int i = 0; i < S; i++) {
        float* p = &g_Hm[nd[i]][off];
        red4(p,     cb[0], cb[1], cb[2], cb[3]);
        red4(p + 4, cb[4], cb[5], cb[6], cb[7]);
    }
}

__global__ void motif_all_kernel(const float* __restrict__ A,
                                 const int* __restrict__ nt, int Mt, int nb3,
                                 const int* __restrict__ nc, int Mc) {
    if ((int)blockIdx.x < nb3)
        motif_body<3>(A, nt, Mt, 0, blockIdx.x);
    else
        motif_body<4>(A, nc, Mc, 1, blockIdx.x - nb3);
}

// ---------------- fused concat + LN + MLP ----------------
// 32 rows/block, 128 threads, 8x8 tile, transposed x,
// cp.async double-buffered W (register-free pipeline).
#define ROWS  32
#define TPB   128
#define BK    8
#define XS    36                  // padded row stride in sXT

__global__ __launch_bounds__(TPB, 4) void mlp_kernel(
    const float* __restrict__ H_in, const float* __restrict__ ln_g,
    const float* __restrict__ ln_b,
    const float* __restrict__ W1, const float* __restrict__ b1,
    const float* __restrict__ W2, const float* __restrict__ b2,
    float* __restrict__ out) {
    __shared__ float sXT[IN_CH * XS];      // [k][row]
    __shared__ float sW[2][BK * HIDD];     // double-buffered W tile

    const int tid  = threadIdx.x;
    const int warp = tid >> 5;
    const int lane = tid & 31;
    const int rbase = blockIdx.x * ROWS;

    const int r0  = warp * 8;
    const int c0a = lane * 4;
    const int c0b = 128 + lane * 4;

    // async tile fetch: 4 x 16B per thread, no registers held
#define CPA_TILE(Wp, kbase, BUF)                                             \
    {                                                                        \
        _Pragma("unroll")                                                    \
        for (int q = 0; q < 4; q++) {                                        \
            int p = q * TPB + tid;                                           \
            int kk = p >> 6, cc = (p & 63) << 2;                             \
            CPA16(&sW[BUF][kk * HIDD + cc],                                  \
                  &Wp[(size_t)((kbase) + kk) * HIDD + cc]);                  \
        }                                                                    \
        CP_COMMIT();                                                         \
    }
#define COMPUTE_TILE(K0, BUF)                                                \
    {                                                                        \
        _Pragma("unroll")                                                    \
        for (int kk = 0; kk < BK; kk++) {                                    \
            const float* xb = &sXT[(K0 + kk) * XS + r0];                     \
            float4 xa = *(const float4*)xb;                                  \
            float4 xc = *(const float4*)(xb + 4);                            \
            unsigned long long xp[8];                                        \
            DUP2(xp[0], __float_as_uint(xa.x));                              \
            DUP2(xp[1], __float_as_uint(xa.y));                              \
            DUP2(xp[2], __float_as_uint(xa.z));                              \
            DUP2(xp[3], __float_as_uint(xa.w));                              \
            DUP2(xp[4], __float_as_uint(xc.x));                              \
            DUP2(xp[5], __float_as_uint(xc.y));                              \
            DUP2(xp[6], __float_as_uint(xc.z));                              \
            DUP2(xp[7], __float_as_uint(xc.w));                              \
            ulonglong2 wA = *(ulonglong2*)&sW[BUF][kk * HIDD + c0a];         \
            ulonglong2 wB = *(ulonglong2*)&sW[BUF][kk * HIDD + c0b];         \
            _Pragma("unroll")                                                \
            for (int i = 0; i < 8; i++) {                                    \
                FFMA2(acc[i][0], xp[i], wA.x);                               \
                FFMA2(acc[i][1], xp[i], wA.y);                               \
                FFMA2(acc[i][2], xp[i], wB.x);                               \
                FFMA2(acc[i][3], xp[i], wB.y);                               \
            }                                                                \
        }                                                                    \
    }

    // kick off W1 tile 0 fetch — latency hides under LN
    CPA_TILE(W1, 0, 0);

    // ---- LN: single gmem read, values kept in registers ----
    {
#pragma unroll
        for (int i = 0; i < 8; i++) {
            int r = r0 + i;
            int grow = rbase + r;
            const float* hrow = H_in + (size_t)grow * D_INc;
            float vloc[9];
            float s = 0.f, s2 = 0.f;
#pragma unroll
            for (int q = 0; q < 9; q++) {
                int c = lane + q * 32;
                if (c < IN_CH) {
                    float v = (c < 16) ? g_Hm[grow][c] : __ldg(hrow + (c - 16));
                    vloc[q] = v;
                    s += v; s2 += v * v;
                }
            }
#pragma unroll
            for (int o = 16; o; o >>= 1) {
                s  += __shfl_xor_sync(0xffffffffu, s, o);
                s2 += __shfl_xor_sync(0xffffffffu, s2, o);
            }
            float mu = s * (1.f / IN_CH);
            float var = s2 * (1.f / IN_CH) - mu * mu;
            float rstd = rsqrtf(var + 1e-5f);
#pragma unroll
            for (int q = 0; q < 9; q++) {
                int c = lane + q * 32;
                if (c < IN_CH)
                    sXT[c * XS + r] = (vloc[q] - mu) * rstd * ln_g[c] + ln_b[c];
            }
        }
    }
    CP_WAIT0();
    __syncthreads();

    unsigned long long acc[8][4];
#pragma unroll
    for (int i = 0; i < 8; i++)
#pragma unroll
        for (int j = 0; j < 4; j++) acc[i][j] = 0ULL;

    // ---- GEMM1: x(32x272) @ W1(272x256), cp.async pipeline ----
    {
        const int NT = IN_CH / BK;       // 34
        for (int t = 0; t < NT; t++) {
            if (t + 1 < NT) CPA_TILE(W1, (t + 1) * BK, (t + 1) & 1);
            COMPUTE_TILE(t * BK, t & 1);
            if (t + 1 < NT) CP_WAIT0();
            __syncthreads();
        }
    }

    // kick off W2 tile 0 fetch — latency hides under GELU math
    CPA_TILE(W2, 0, 0);

    // ---- bias + exact GELU -> transposed hidden into sXT ----
    {
        const float4 bA = *(const float4*)&b1[c0a];
        const float4 bB = *(const float4*)&b1[c0b];
        const float bb[8] = {bA.x, bA.y, bA.z, bA.w, bB.x, bB.y, bB.z, bB.w};
        float v[8][8];
#pragma unroll
        for (int i = 0; i < 8; i++)
#pragma unroll
            for (int j = 0; j < 4; j++) {
                unsigned lo, hi;
                UNPK2(lo, hi, acc[i][j]);
                float x0 = __uint_as_float(lo) + bb[j * 2];
                float x1 = __uint_as_float(hi) + bb[j * 2 + 1];
                v[i][j * 2]     = 0.5f * x0 * (1.f + erff(x0 * 0.7071067811865475f));
                v[i][j * 2 + 1] = 0.5f * x1 * (1.f + erff(x1 * 0.7071067811865475f));
                acc[i][j] = 0ULL;
            }
#pragma unroll
        for (int j = 0; j < 8; j++) {
            int c = (j < 4) ? (c0a + j) : (c0b + j - 4);
            *(float4*)&sXT[c * XS + r0] =
                make_float4(v[0][j], v[1][j], v[2][j], v[3][j]);
            *(float4*)&sXT[c * XS + r0 + 4] =
                make_float4(v[4][j], v[5][j], v[6][j], v[7][j]);
        }
    }
    CP_WAIT0();
    __syncthreads();

    // ---- GEMM2: h(32x256) @ W2(256x256) ----
    {
        const int NT = HIDD / BK;        // 32
        for (int t = 0; t < NT; t++) {
            if (t + 1 < NT) CPA_TILE(W2, (t + 1) * BK, (t + 1) & 1);
            COMPUTE_TILE(t * BK, t & 1);
            if (t + 1 < NT) CP_WAIT0();
            __syncthreads();
        }
    }

    // ---- bias + store ----
    {
        const float4 bA = *(const float4*)&b2[c0a];
        const float4 bB = *(const float4*)&b2[c0b];
#pragma unroll
        for (int i = 0; i < 8; i++) {
            unsigned lo, hi;
            float v[8];
#pragma unroll
            for (int j = 0; j < 4; j++) {
                UNPK2(lo, hi, acc[i][j]);
                v[j * 2]     = __uint_as_float(lo);
                v[j * 2 + 1] = __uint_as_float(hi);
            }
            size_t base = (size_t)(rbase + r0 + i) * D_OUTc;
            *(float4*)&out[base + c0a] =
                make_float4(v[0] + bA.x, v[1] + bA.y, v[2] + bA.z, v[3] + bA.w);
            *(float4*)&out[base + c0b] =
                make_float4(v[4] + bB.x, v[5] + bB.y, v[6] + bB.z, v[7] + bB.w);
        }
    }
}

// ---------------- launch ----------------
extern "C" void kernel_launch(void* const* d_in, const int* in_sizes, int n_in,
                              void* d_out, int out_size) {
    const float* A       = (const float*)d_in[0];
    const float* H_in    = (const float*)d_in[1];
    const float* Wt      = (const float*)d_in[2];
    const float* Wc      = (const float*)d_in[3];
    const float* lg      = (const float*)d_in[4];
    const float* ln_g    = (const float*)d_in[5];
    const float* ln_b    = (const float*)d_in[6];
    const float* W1      = (const float*)d_in[7];
    const float* b1      = (const float*)d_in[8];
    const float* W2      = (const float*)d_in[9];
    const float* b2      = (const float*)d_in[10];
    const int* nodes_tri = (const int*)d_in[11];
    const int* nodes_cl4 = (const int*)d_in[12];
    float* out = (float*)d_out;

    int M_tri = in_sizes[11] / 3;
    int M_cl4 = in_sizes[12] / 4;
    int nb3 = (M_tri + 255) / 256;
    int nb4 = (M_cl4 + 255) / 256;

    setup_kernel<<<1, 32>>>(Wt, Wc, lg);
    zero_kernel<<<(Nn * 16 + 255) / 256, 256>>>();
    motif_all_kernel<<<nb3 + nb4, 256>>>(A, nodes_tri, M_tri, nb3, nodes_cl4, M_cl4);
    mlp_kernel<<<Nn / ROWS, TPB>>>(H_in, ln_g, ln_b, W1, b1, W2, b2, out);
}